// round 10
// baseline (speedup 1.0000x reference)
#include <cuda_runtime.h>
#include <cstdint>

#define M_ROWS 16384
#define IN_F   2048
#define OUT_F  2048

// Exact identity: out[m,n] = rowsum(x[m]) - 2 * sum_{k: w[n,k] < 0} x[m,k]
// (b_weight = sign(sign(w)+0.5) is -1 iff w < 0, else +1 including w == 0).
//
// Negative-index lists: 8 independent 256-element segments per weight row
// (segment s covers k in [s*256, (s+1)*256)); each warp compacts its own
// segment. Fast path: rows with no negative entries skip compaction entirely.

__device__ unsigned short g_neg_idx[(size_t)OUT_F * IN_F];   // 8 MB scratch
__device__ unsigned short g_seg_cnt[(size_t)OUT_F * 8];      // per-segment counts
__device__ unsigned char  g_neg_flag[OUT_F];                 // 1 iff any negative

// ---------------------------------------------------------------------------
// K1: weight scan. Block per weight row (2048 blocks); warp per 256-elem
// segment. Triggers PDL completion immediately so K2 can launch and overlap
// its rowsum phase with this scan.
// ---------------------------------------------------------------------------
__global__ void __launch_bounds__(256) scan_kernel(const float* __restrict__ w)
{
    cudaTriggerProgrammaticLaunchCompletion();

    const int n    = blockIdx.x;
    const int warp = threadIdx.x >> 5;
    const int lane = threadIdx.x & 31;
    const unsigned lt_mask = (1u << lane) - 1u;

    const float4* wr = reinterpret_cast<const float4*>(w + (size_t)n * IN_F);

    // Each thread owns float4 elements i4a, i4b of the row.
    const int i4a = warp * 64 + lane;
    const int i4b = i4a + 32;
    const float4 va = wr[i4a];
    const float4 vb = wr[i4b];

    const bool nega = (va.x < 0.0f) | (va.y < 0.0f) | (va.z < 0.0f) | (va.w < 0.0f);
    const bool negb = (vb.x < 0.0f) | (vb.y < 0.0f) | (vb.z < 0.0f) | (vb.w < 0.0f);

    const int any_neg = __syncthreads_or(nega | negb);
    if (!any_neg) {
        if (threadIdx.x == 0) g_neg_flag[n] = 0;
        return;
    }

    // Slow path: ballot-compact per-warp segments.
    __shared__ int s_cnt[8];
    unsigned short* idx = g_neg_idx + (size_t)n * IN_F + warp * 256;
    int cnt = 0;

    #pragma unroll
    for (int half = 0; half < 2; half++) {
        const float4 v = half ? vb : va;
        const int kb = (half ? i4b : i4a) * 4;
        unsigned b;
        b = __ballot_sync(0xffffffffu, v.x < 0.0f);
        if (v.x < 0.0f) idx[cnt + __popc(b & lt_mask)] = (unsigned short)(kb + 0);
        cnt += __popc(b);
        b = __ballot_sync(0xffffffffu, v.y < 0.0f);
        if (v.y < 0.0f) idx[cnt + __popc(b & lt_mask)] = (unsigned short)(kb + 1);
        cnt += __popc(b);
        b = __ballot_sync(0xffffffffu, v.z < 0.0f);
        if (v.z < 0.0f) idx[cnt + __popc(b & lt_mask)] = (unsigned short)(kb + 2);
        cnt += __popc(b);
        b = __ballot_sync(0xffffffffu, v.w < 0.0f);
        if (v.w < 0.0f) idx[cnt + __popc(b & lt_mask)] = (unsigned short)(kb + 3);
        cnt += __popc(b);
    }
    if (lane == 0) s_cnt[warp] = cnt;
    __syncthreads();

    if (threadIdx.x < 8)
        g_seg_cnt[(size_t)n * 8 + threadIdx.x] = (unsigned short)s_cnt[threadIdx.x];
    if (threadIdx.x == 0)
        g_neg_flag[n] = 1;
}

// ---------------------------------------------------------------------------
// K2: fused read-reduce-write. Warp per x row (8 rows/block, 2048 blocks).
// Launched with PDL: rowsum phase overlaps the scan; grid-dependency sync
// before any flag/count/index consumption.
// ---------------------------------------------------------------------------
__global__ void __launch_bounds__(256) out_kernel(
    const float* __restrict__ x,
    float*       __restrict__ out)
{
    const int warp = threadIdx.x >> 5;
    const int lane = threadIdx.x & 31;
    const int m = blockIdx.x * 8 + warp;

    const float* xrow = x + (size_t)m * IN_F;
    const float4* xr4 = reinterpret_cast<const float4*>(xrow);
    float4* orow = reinterpret_cast<float4*>(out + (size_t)m * OUT_F);

    // Phase B: rowsum — independent of the scan, overlaps it under PDL.
    float s0 = 0.0f, s1 = 0.0f;
    #pragma unroll
    for (int it = 0; it < 16; it += 2) {
        const float4 a = xr4[it * 32 + lane];
        const float4 b = xr4[(it + 1) * 32 + lane];
        s0 += (a.x + a.y) + (a.z + a.w);
        s1 += (b.x + b.y) + (b.z + b.w);
    }
    float s = s0 + s1;
    #pragma unroll
    for (int o = 16; o > 0; o >>= 1)
        s += __shfl_xor_sync(0xffffffffu, s, o);
    const float S = s;

    // Wait for the scan kernel's writes to be visible.
    cudaGridDependencySynchronize();

    __shared__ unsigned char sflag[OUT_F];
    const unsigned long long fchunk =
        reinterpret_cast<const unsigned long long*>(g_neg_flag)[threadIdx.x];
    const int any_neg = __syncthreads_or(fchunk != 0ull);

    if (!any_neg) {
        // Pure splat: 16 coalesced STG.128 per lane.
        const float4 v = make_float4(S, S, S, S);
        #pragma unroll
        for (int it = 0; it < 16; it++)
            orow[it * 32 + lane] = v;
    } else {
        reinterpret_cast<unsigned long long*>(sflag)[threadIdx.x] = fchunk;
        __syncthreads();
        for (int it = 0; it < 16; it++) {
            const int i4 = it * 32 + lane;
            const int n0 = i4 * 4;
            float4 v = make_float4(S, S, S, S);
            const uchar4 f = *reinterpret_cast<const uchar4*>(sflag + n0);
            if (f.x | f.y | f.z | f.w) {
                float* vc = reinterpret_cast<float*>(&v);
                const unsigned char* fc = reinterpret_cast<const unsigned char*>(&f);
                #pragma unroll
                for (int e = 0; e < 4; e++) {
                    if (fc[e]) {
                        const int n = n0 + e;
                        float c = 0.0f;
                        const unsigned short* base = g_neg_idx + (size_t)n * IN_F;
                        const unsigned short* scnt = g_seg_cnt + (size_t)n * 8;
                        #pragma unroll
                        for (int sgi = 0; sgi < 8; sgi++) {
                            const int cnt = scnt[sgi];
                            const unsigned short* id = base + sgi * 256;
                            for (int j = 0; j < cnt; j++) c += __ldg(xrow + id[j]);
                        }
                        vc[e] = S - 2.0f * c;
                    }
                }
            }
            orow[i4] = v;
        }
    }
}

// ---------------------------------------------------------------------------
// d_in[0] = x [M, IN_F] fp32, d_in[1] = weight [OUT_F, IN_F] fp32.
// d_out = [M, OUT_F] fp32.
// ---------------------------------------------------------------------------
extern "C" void kernel_launch(void* const* d_in, const int* in_sizes, int n_in,
                              void* d_out, int out_size)
{
    const float* x = (const float*)d_in[0];
    const float* w = (const float*)d_in[1];
    float* out = (float*)d_out;

    scan_kernel<<<OUT_F, 256>>>(w);

    // PDL launch: out_kernel may begin once scan_kernel triggers; its
    // rowsum phase overlaps the scan, and cudaGridDependencySynchronize()
    // guards the flag/index consumption.
    cudaLaunchConfig_t cfg = {};
    cfg.gridDim  = dim3(M_ROWS / 8);
    cfg.blockDim = dim3(256);
    cfg.dynamicSmemBytes = 0;
    cfg.stream = 0;
    cudaLaunchAttribute attrs[1];
    attrs[0].id = cudaLaunchAttributeProgrammaticStreamSerialization;
    attrs[0].val.programmaticStreamSerializationAllowed = 1;
    cfg.attrs = attrs;
    cfg.numAttrs = 1;
    cudaLaunchKernelEx(&cfg, out_kernel, x, out);
}

// round 11
// speedup vs baseline: 1.1756x; 1.1756x over previous
#include <cuda_runtime.h>
#include <cstdint>

#define M_ROWS 16384
#define IN_F   2048
#define OUT_F  2048

// Exact identity: out[m,n] = rowsum(x[m]) - 2 * sum_{k: w[n,k] < 0} x[m,k]
// (b_weight = sign(sign(w)+0.5) is -1 iff w < 0, else +1 including w == 0).
//
// Negative-index lists: 8 independent 256-element segments per weight row
// (segment s covers k in [s*256, (s+1)*256)); each warp compacts its own
// segment. Fast path: rows with no negative entries skip compaction entirely.

__device__ unsigned short g_neg_idx[(size_t)OUT_F * IN_F];   // 8 MB scratch
__device__ unsigned short g_seg_cnt[(size_t)OUT_F * 8];      // per-segment counts
__device__ unsigned char  g_neg_flag[OUT_F];                 // 1 iff any negative

// ---------------------------------------------------------------------------
// K1: weight scan. Block per weight row (2048 blocks); warp per 256-elem
// segment. Triggers PDL completion immediately so K2 can launch and overlap
// its rowsum phase with this scan.
// ---------------------------------------------------------------------------
__global__ void __launch_bounds__(256) scan_kernel(const float* __restrict__ w)
{
    cudaTriggerProgrammaticLaunchCompletion();

    const int n    = blockIdx.x;
    const int warp = threadIdx.x >> 5;
    const int lane = threadIdx.x & 31;
    const unsigned lt_mask = (1u << lane) - 1u;

    const float4* wr = reinterpret_cast<const float4*>(w + (size_t)n * IN_F);

    // Each thread owns float4 elements i4a, i4b of the row.
    const int i4a = warp * 64 + lane;
    const int i4b = i4a + 32;
    const float4 va = wr[i4a];
    const float4 vb = wr[i4b];

    const bool nega = (va.x < 0.0f) | (va.y < 0.0f) | (va.z < 0.0f) | (va.w < 0.0f);
    const bool negb = (vb.x < 0.0f) | (vb.y < 0.0f) | (vb.z < 0.0f) | (vb.w < 0.0f);

    const int any_neg = __syncthreads_or(nega | negb);
    if (!any_neg) {
        if (threadIdx.x == 0) g_neg_flag[n] = 0;
        return;
    }

    // Slow path: ballot-compact per-warp segments.
    __shared__ int s_cnt[8];
    unsigned short* idx = g_neg_idx + (size_t)n * IN_F + warp * 256;
    int cnt = 0;

    #pragma unroll
    for (int half = 0; half < 2; half++) {
        const float4 v = half ? vb : va;
        const int kb = (half ? i4b : i4a) * 4;
        unsigned b;
        b = __ballot_sync(0xffffffffu, v.x < 0.0f);
        if (v.x < 0.0f) idx[cnt + __popc(b & lt_mask)] = (unsigned short)(kb + 0);
        cnt += __popc(b);
        b = __ballot_sync(0xffffffffu, v.y < 0.0f);
        if (v.y < 0.0f) idx[cnt + __popc(b & lt_mask)] = (unsigned short)(kb + 1);
        cnt += __popc(b);
        b = __ballot_sync(0xffffffffu, v.z < 0.0f);
        if (v.z < 0.0f) idx[cnt + __popc(b & lt_mask)] = (unsigned short)(kb + 2);
        cnt += __popc(b);
        b = __ballot_sync(0xffffffffu, v.w < 0.0f);
        if (v.w < 0.0f) idx[cnt + __popc(b & lt_mask)] = (unsigned short)(kb + 3);
        cnt += __popc(b);
    }
    if (lane == 0) s_cnt[warp] = cnt;
    __syncthreads();

    if (threadIdx.x < 8)
        g_seg_cnt[(size_t)n * 8 + threadIdx.x] = (unsigned short)s_cnt[threadIdx.x];
    if (threadIdx.x == 0)
        g_neg_flag[n] = 1;
}

// ---------------------------------------------------------------------------
// K2: fused read-reduce-write. Warp per x row (8 rows/block, 2048 blocks).
// Launched with PDL: rowsum phase overlaps the scan; grid-dependency sync
// before any flag/count/index consumption.
// ---------------------------------------------------------------------------
__global__ void __launch_bounds__(256) out_kernel(
    const float* __restrict__ x,
    float*       __restrict__ out)
{
    const int warp = threadIdx.x >> 5;
    const int lane = threadIdx.x & 31;
    const int m = blockIdx.x * 8 + warp;

    const float* xrow = x + (size_t)m * IN_F;
    const float4* xr4 = reinterpret_cast<const float4*>(xrow);
    float4* orow = reinterpret_cast<float4*>(out + (size_t)m * OUT_F);

    // Phase B: rowsum — independent of the scan, overlaps it under PDL.
    float s0 = 0.0f, s1 = 0.0f;
    #pragma unroll
    for (int it = 0; it < 16; it += 2) {
        const float4 a = xr4[it * 32 + lane];
        const float4 b = xr4[(it + 1) * 32 + lane];
        s0 += (a.x + a.y) + (a.z + a.w);
        s1 += (b.x + b.y) + (b.z + b.w);
    }
    float s = s0 + s1;
    #pragma unroll
    for (int o = 16; o > 0; o >>= 1)
        s += __shfl_xor_sync(0xffffffffu, s, o);
    const float S = s;

    // Wait for the scan kernel's writes to be visible.
    cudaGridDependencySynchronize();

    __shared__ unsigned char sflag[OUT_F];
    const unsigned long long fchunk =
        reinterpret_cast<const unsigned long long*>(g_neg_flag)[threadIdx.x];
    const int any_neg = __syncthreads_or(fchunk != 0ull);

    if (!any_neg) {
        // Pure splat: 16 coalesced STG.128 per lane.
        const float4 v = make_float4(S, S, S, S);
        #pragma unroll
        for (int it = 0; it < 16; it++)
            orow[it * 32 + lane] = v;
    } else {
        reinterpret_cast<unsigned long long*>(sflag)[threadIdx.x] = fchunk;
        __syncthreads();
        for (int it = 0; it < 16; it++) {
            const int i4 = it * 32 + lane;
            const int n0 = i4 * 4;
            float4 v = make_float4(S, S, S, S);
            const uchar4 f = *reinterpret_cast<const uchar4*>(sflag + n0);
            if (f.x | f.y | f.z | f.w) {
                float* vc = reinterpret_cast<float*>(&v);
                const unsigned char* fc = reinterpret_cast<const unsigned char*>(&f);
                #pragma unroll
                for (int e = 0; e < 4; e++) {
                    if (fc[e]) {
                        const int n = n0 + e;
                        float c = 0.0f;
                        const unsigned short* base = g_neg_idx + (size_t)n * IN_F;
                        const unsigned short* scnt = g_seg_cnt + (size_t)n * 8;
                        #pragma unroll
                        for (int sgi = 0; sgi < 8; sgi++) {
                            const int cnt = scnt[sgi];
                            const unsigned short* id = base + sgi * 256;
                            for (int j = 0; j < cnt; j++) c += __ldg(xrow + id[j]);
                        }
                        vc[e] = S - 2.0f * c;
                    }
                }
            }
            orow[i4] = v;
        }
    }
}

// ---------------------------------------------------------------------------
// d_in[0] = x [M, IN_F] fp32, d_in[1] = weight [OUT_F, IN_F] fp32.
// d_out = [M, OUT_F] fp32.
// ---------------------------------------------------------------------------
extern "C" void kernel_launch(void* const* d_in, const int* in_sizes, int n_in,
                              void* d_out, int out_size)
{
    const float* x = (const float*)d_in[0];
    const float* w = (const float*)d_in[1];
    float* out = (float*)d_out;

    scan_kernel<<<OUT_F, 256>>>(w);

    // PDL launch: out_kernel may begin once scan_kernel triggers; its
    // rowsum phase overlaps the scan, and cudaGridDependencySynchronize()
    // guards the flag/index consumption.
    cudaLaunchConfig_t cfg = {};
    cfg.gridDim  = dim3(M_ROWS / 8);
    cfg.blockDim = dim3(256);
    cfg.dynamicSmemBytes = 0;
    cfg.stream = 0;
    cudaLaunchAttribute attrs[1];
    attrs[0].id = cudaLaunchAttributeProgrammaticStreamSerialization;
    attrs[0].val.programmaticStreamSerializationAllowed = 1;
    cfg.attrs = attrs;
    cfg.numAttrs = 1;
    cudaLaunchKernelEx(&cfg, out_kernel, x, out);
}